// round 10
// baseline (speedup 1.0000x reference)
#include <cuda_runtime.h>

#define WS 8
#define BB 64
#define TT 256
#define HH 64
#define NW 248

typedef unsigned long long u64;

__device__ __forceinline__ void fma2(u64 &acc, u64 a, u64 b) {
    asm("fma.rn.f32x2 %0, %1, %2, %0;" : "+l"(acc) : "l"(a), "l"(b));
}
__device__ __forceinline__ void add2(u64 &a, u64 b) {
    asm("add.rn.f32x2 %0, %1, %2;" : "=l"(a) : "l"(a), "l"(b));
}
__device__ __forceinline__ u64 pack2(float a, float b) {
    u64 r; asm("mov.b64 %0, {%1, %2};" : "=l"(r) : "f"(a), "f"(b)); return r;
}
__device__ __forceinline__ float lo_f(u64 v) { return __uint_as_float((unsigned)v); }
__device__ __forceinline__ float hi_f(u64 v) { return __uint_as_float((unsigned)(v >> 32)); }
__device__ __forceinline__ float hsum(u64 v) { return lo_f(v) + hi_f(v); }
__device__ __forceinline__ float tanh_ap(float x) {
    float y; asm("tanh.approx.f32 %0, %1;" : "=f"(y) : "f"(x)); return y;
}
__device__ __forceinline__ u64 shflx(u64 v, int mask) {
    unsigned lo = (unsigned)v, hi = (unsigned)(v >> 32);
    lo = __shfl_xor_sync(0xffffffffu, lo, mask);
    hi = __shfl_xor_sync(0xffffffffu, hi, mask);
    return ((u64)hi << 32) | lo;
}
__device__ __forceinline__ u64 red_sl(u64 v) {   // sum over the 4 sl lanes
    add2(v, shflx(v, 1)); add2(v, shflx(v, 2)); return v;
}

__device__ __forceinline__ float xin_value(const float* trajs, const float* preds,
                                           int w, int s, int f) {
    if (w == 0) return trajs[s * 4 + f];
    if (w < WS) {
        if (s < WS - w) return trajs[(w + s) * 4 + f];
        return (f < 2) ? trajs[(2 * w + s - 1) * 4 + f]
                       : preds[(w + s - WS) * 2 + (f - 2)];
    }
    return (f < 2) ? trajs[(w + s) * 4 + f]
                   : preds[(w + s - WS) * 2 + (f - 2)];
}

__global__ __launch_bounds__(512, 1)
void or_lstm_kernel(const float* __restrict__ traj,
                    const float* __restrict__ Wih0, const float* __restrict__ Whh0,
                    const float* __restrict__ bih0, const float* __restrict__ bhh0,
                    const float* __restrict__ Wih1, const float* __restrict__ Whh1,
                    const float* __restrict__ bih1, const float* __restrict__ bhh1,
                    const float* __restrict__ Wlin, const float* __restrict__ blin,
                    float* __restrict__ out)
{
    const int b    = blockIdx.x;
    const int tid  = threadIdx.x;
    const int lane = tid & 31;
    const int wid  = tid >> 5;       // 16 warps
    const int m    = tid >> 3;       // h-index (0..63)
    const int p    = (tid >> 2) & 1; // gate pair: 0 -> (i,f), 1 -> (g,o)
    const int sl   = tid & 3;        // 16-k slice
    const int L    = tid & 7;        // lane within the 8-thread m-group

    __shared__ __align__(16) float trajs[TT * 4];
    __shared__ __align__(16) float h0s[2][HH], h1s[2][HH];
    __shared__ __align__(16) u64 xgb[WS][2][HH];    // bias0 + Wih0·x, per gate pair
    __shared__ __align__(16) u64 wp_s[2][HH][4];    // Wih0 packed by gate pair
    __shared__ __align__(16) u64 bp_s[2][HH];       // layer-0 bias (packed pair)
    __shared__ __align__(16) u64 b1_s[2][HH];       // layer-1 bias (packed pair)
    __shared__ float wlin_s[2][HH];
    __shared__ float preds[NW * 2];
    __shared__ float predpart[32];
    __shared__ float blin_s[2];

    for (int i = tid; i < TT * 4; i += 512) trajs[i] = traj[b * TT * 4 + i];
    if (tid < 2) blin_s[tid] = blin[tid];
    {   // Wih0 table: (pair, m, feature) -> pack2(gate 2p row, gate 2p+1 row)
        const int pt = tid >> 8, mm = (tid >> 2) & 63, f = tid & 3;
        wp_s[pt][mm][f] = pack2(Wih0[(128 * pt + mm) * 4 + f],
                                Wih0[(128 * pt + 64 + mm) * 4 + f]);
    }
    if (tid < 128) {
        const int pt = tid >> 6, mm = tid & 63;
        bp_s[pt][mm] = pack2(bih0[128 * pt + mm] + bhh0[128 * pt + mm],
                             bih0[128 * pt + 64 + mm] + bhh0[128 * pt + 64 + mm]);
        b1_s[pt][mm] = pack2(bih1[128 * pt + mm] + bhh1[128 * pt + mm],
                             bih1[128 * pt + 64 + mm] + bhh1[128 * pt + 64 + mm]);
        wlin_s[pt][mm] = Wlin[pt * 64 + mm];
    }

    // ---- recurrent weights -> regs: thread owns gates {2p, 2p+1}, k-slice sl ----
    u64 whh0r[2][8], wih1r[2][8], whh1r[2][8];
    #pragma unroll
    for (int e = 0; e < 2; e++) {
        const int rg = 128 * p + 64 * e + m;
        #pragma unroll
        for (int c = 0; c < 4; c++) {
            const int k0 = 16 * c + 4 * sl;
            ulonglong2 v0 = *(const ulonglong2*)(Whh0 + rg * HH + k0);
            whh0r[e][2 * c] = v0.x; whh0r[e][2 * c + 1] = v0.y;
            ulonglong2 v1 = *(const ulonglong2*)(Wih1 + rg * HH + k0);
            wih1r[e][2 * c] = v1.x; wih1r[e][2 * c + 1] = v1.y;
            ulonglong2 v2 = *(const ulonglong2*)(Whh1 + rg * HH + k0);
            whh1r[e][2 * c] = v2.x; whh1r[e][2 * c + 1] = v2.y;
        }
    }

    float c0 = 0.f, c1 = 0.f, h0v = 0.f, h1v = 0.f;

    // single dot: acc += W · h_slice (8 fma2)
    auto dot16 = [&](u64 acc[2], const float* hbuf, const u64 (&w)[2][8]) {
        #pragma unroll
        for (int c = 0; c < 4; c++) {
            ulonglong2 hv = *(const ulonglong2*)(hbuf + 16 * c + 4 * sl);
            fma2(acc[0], hv.x, w[0][2 * c]); fma2(acc[0], hv.y, w[0][2 * c + 1]);
            fma2(acc[1], hv.x, w[1][2 * c]); fma2(acc[1], hv.y, w[1][2 * c + 1]);
        }
    };
    // fused dual dot sharing the h0 loads: a1 += Wih1·h0, a0 += Whh0·h0
    auto dot16_dual = [&](u64 a1[2], u64 a0[2], const float* hbuf) {
        #pragma unroll
        for (int c = 0; c < 4; c++) {
            ulonglong2 hv = *(const ulonglong2*)(hbuf + 16 * c + 4 * sl);
            fma2(a1[0], hv.x, wih1r[0][2 * c]); fma2(a1[0], hv.y, wih1r[0][2 * c + 1]);
            fma2(a1[1], hv.x, wih1r[1][2 * c]); fma2(a1[1], hv.y, wih1r[1][2 * c + 1]);
            fma2(a0[0], hv.x, whh0r[0][2 * c]); fma2(a0[0], hv.y, whh0r[0][2 * c + 1]);
            fma2(a0[1], hv.x, whh0r[1][2 * c]); fma2(a0[1], hv.y, whh0r[1][2 * c + 1]);
        }
    };
    // A holds reduced gate sums (lo = gate 2p, hi = gate 2p+1); lane does 1 act
    auto cell = [&](u64 A, float &c, bool first) -> float {
        float arg = (sl & 1) ? hi_f(A) : lo_f(A);
        const bool tg = (p == 1) && !(sl & 1);     // tanh gate (g)
        const float kmv = tg ? 1.0f : 0.5f;
        const float kbv = tg ? 0.0f : 0.5f;
        float act = fmaf(kmv, tanh_ap(kmv * arg), kbv);
        const unsigned base = lane & ~7u;
        float iv = __shfl_sync(0xffffffffu, act, base + 0);
        float fv = __shfl_sync(0xffffffffu, act, base + 1);
        float gv = __shfl_sync(0xffffffffu, act, base + 4);
        float ov = __shfl_sync(0xffffffffu, act, base + 5);
        c = first ? iv * gv : fmaf(fv, c, iv * gv);
        return ov * tanh_ap(c);
    };
    // one warp builds one xgb row; only one px register pair live at a time
    auto xgb_row = [&](int w, int s) {
        float xf = (lane < 4) ? xin_value(trajs, preds, w, s, lane) : 0.0f;
        #pragma unroll
        for (int r = 0; r < 2; r++) {
            const int mm = lane + 32 * r;
            u64 a01 = bp_s[0][mm], a23 = bp_s[1][mm];
            #pragma unroll
            for (int f = 0; f < 4; f++) {
                float x = __shfl_sync(0xffffffffu, xf, f);
                u64 px = pack2(x, x);
                fma2(a01, px, wp_s[0][mm][f]);
                fma2(a23, px, wp_s[1][mm][f]);
            }
            xgb[s][0][mm] = a01; xgb[s][1][mm] = a23;
        }
    };

    __syncthreads();                 // trajs + tables staged
    if (wid < 8) xgb_row(0, wid);    // window 0 rows (pure traj)
    __syncthreads();

    for (int w = 0; w < NW; w++) {
        // ===== phase 0: P0(0); side: warp15 builds xgb row 7 (needs pred[w-1])
        {
            u64 A0 = xgb[0][p][m];
            h0v = cell(A0, c0, true);
            if (L == 0) h0s[0][m] = h0v;
            if (w > 0 && wid == 15) xgb_row(w, 7);
        }
        __syncthreads();

        // ===== phase 1: P1(0) + P0(1)
        {
            u64 a1[2] = {0, 0}, a0[2] = {0, 0};
            dot16_dual(a1, a0, h0s[0]);
            u64 A1 = red_sl(pack2(hsum(a1[0]), hsum(a1[1]))); add2(A1, b1_s[p][m]);
            h1v = cell(A1, c1, true);
            if (L == 0) h1s[0][m] = h1v;
            u64 A0 = red_sl(pack2(hsum(a0[0]), hsum(a0[1]))); add2(A0, xgb[1][p][m]);
            h0v = cell(A0, c0, false);
            if (L == 0) h0s[1][m] = h0v;
        }
        __syncthreads();

        // ===== phases 2..7: P1(s-1) + P0(s)
        #pragma unroll 2
        for (int s = 2; s < WS; s++) {
            const int ps = s & 1, pp = ps ^ 1;
            u64 a1[2] = {0, 0}, a0[2] = {0, 0};
            dot16_dual(a1, a0, h0s[pp]);     // h0(s-1): feeds both layers
            dot16(a1, h1s[ps], whh1r);       // h1(s-2)
            u64 A1 = red_sl(pack2(hsum(a1[0]), hsum(a1[1]))); add2(A1, b1_s[p][m]);
            h1v = cell(A1, c1, false);
            if (L == 0) h1s[pp][m] = h1v;    // h1(s-1)
            u64 A0 = red_sl(pack2(hsum(a0[0]), hsum(a0[1]))); add2(A0, xgb[s][p][m]);
            h0v = cell(A0, c0, false);
            if (L == 0) h0s[ps][m] = h0v;    // h0(s)
            __syncthreads();
        }

        // ===== phase 8: P1(7) + pred partial (h1v live in all lanes)
        {
            u64 a1[2] = {0, 0};
            dot16(a1, h0s[1], wih1r);        // h0(7)
            dot16(a1, h1s[0], whh1r);        // h1(6)
            u64 A1 = red_sl(pack2(hsum(a1[0]), hsum(a1[1]))); add2(A1, b1_s[p][m]);
            h1v = cell(A1, c1, false);
            if (L == 0) h1s[1][m] = h1v;
            float pv = wlin_s[p][m] * h1v;   // row p of Wlin, this m
            pv += __shfl_xor_sync(0xffffffffu, pv, 8);
            pv += __shfl_xor_sync(0xffffffffu, pv, 16);
            if ((lane & 3) == 0) predpart[wid * 2 + p] = pv;
        }
        __syncthreads();

        // ===== phase F: warps 8..14 build xgb rows 0..6 of w+1; warp15 finalizes pred[w]
        if (wid >= 8 && wid < 15) {
            if (w + 1 < NW) xgb_row(w + 1, wid - 8);
        } else if (wid == 15 && lane < 2) {
            float d = blin_s[lane];
            #pragma unroll
            for (int k = 0; k < 16; k++) d += predpart[k * 2 + lane];
            const float prev = (w == 0) ? trajs[7 * 4 + 2 + lane]
                                        : preds[(w - 1) * 2 + lane];
            const float pr = prev + d;
            preds[w * 2 + lane] = pr;
            out[(b * NW + w) * 2 + lane] = pr;
        }
        __syncthreads();
    }

    // ---- final states: h[2,B,H] then c[2,B,H] (all lanes hold h/c; L==0 writes) ----
    if (L == 0) {
        const int base = BB * NW * 2;
        out[base + 0 * BB * HH + b * HH + m] = h0v;
        out[base + 1 * BB * HH + b * HH + m] = h1v;
        out[base + 2 * BB * HH + b * HH + m] = c0;
        out[base + 3 * BB * HH + b * HH + m] = c1;
    }
}

extern "C" void kernel_launch(void* const* d_in, const int* in_sizes, int n_in,
                              void* d_out, int out_size) {
    const float* traj = (const float*)d_in[0];
    const float* Wih0 = (const float*)d_in[1];
    const float* Whh0 = (const float*)d_in[2];
    const float* bih0 = (const float*)d_in[3];
    const float* bhh0 = (const float*)d_in[4];
    const float* Wih1 = (const float*)d_in[5];
    const float* Whh1 = (const float*)d_in[6];
    const float* bih1 = (const float*)d_in[7];
    const float* bhh1 = (const float*)d_in[8];
    const float* Wlin = (const float*)d_in[9];
    const float* blin = (const float*)d_in[10];

    or_lstm_kernel<<<BB, 512>>>(traj, Wih0, Whh0, bih0, bhh0,
                                Wih1, Whh1, bih1, bhh1,
                                Wlin, blin, (float*)d_out);
}

// round 11
// speedup vs baseline: 1.3738x; 1.3738x over previous
#include <cuda_runtime.h>

#define WS 8
#define BB 64
#define TT 256
#define HH 64
#define NW 248

typedef unsigned long long u64;

__device__ __forceinline__ void fma2(u64 &acc, u64 a, u64 b) {
    asm("fma.rn.f32x2 %0, %1, %2, %0;" : "+l"(acc) : "l"(a), "l"(b));
}
__device__ __forceinline__ void add2(u64 &a, u64 b) {
    asm("add.rn.f32x2 %0, %1, %2;" : "=l"(a) : "l"(a), "l"(b));
}
__device__ __forceinline__ u64 pack2(float a, float b) {
    u64 r; asm("mov.b64 %0, {%1, %2};" : "=l"(r) : "f"(a), "f"(b)); return r;
}
__device__ __forceinline__ float lo_f(u64 v) { return __uint_as_float((unsigned)v); }
__device__ __forceinline__ float hi_f(u64 v) { return __uint_as_float((unsigned)(v >> 32)); }
__device__ __forceinline__ float hsum(u64 v) { return lo_f(v) + hi_f(v); }
__device__ __forceinline__ float tanh_ap(float x) {
    float y; asm("tanh.approx.f32 %0, %1;" : "=f"(y) : "f"(x)); return y;
}
__device__ __forceinline__ u64 shflx(u64 v, int mask) {
    unsigned lo = (unsigned)v, hi = (unsigned)(v >> 32);
    lo = __shfl_xor_sync(0xffffffffu, lo, mask);
    hi = __shfl_xor_sync(0xffffffffu, hi, mask);
    return ((u64)hi << 32) | lo;
}
__device__ __forceinline__ u64 reduce_pair(u64 v) {
    add2(v, shflx(v, 1)); add2(v, shflx(v, 2)); return v;
}

// acc[g] += W[g] · h_slice (16 k-elements, chunks 16c+4sl)
__device__ __forceinline__ void dot64(u64 acc[4], const float* __restrict__ hbuf,
                                      const u64 (&w)[4][4][2], int sl) {
    #pragma unroll
    for (int c = 0; c < 4; c++) {
        ulonglong2 hv = *(const ulonglong2*)(hbuf + 16 * c + 4 * sl);
        #pragma unroll
        for (int g = 0; g < 4; g++) {
            fma2(acc[g], hv.x, w[g][c][0]);
            fma2(acc[g], hv.y, w[g][c][1]);
        }
    }
}
// lane sl computes only its own gate's activation (1 MUFU)
__device__ __forceinline__ float gate_act(u64 A, u64 B, int sl, float km, float kb) {
    float arg = (sl & 2) ? ((sl & 1) ? hi_f(B) : lo_f(B))
                         : ((sl & 1) ? hi_f(A) : lo_f(A));
    return fmaf(km, tanh_ap(km * arg), kb);
}
// gather gates into lane 0 of each 4-lane group; c/h valid in lane 0 only
__device__ __forceinline__ float cell_from_act(float act, float &c, bool first) {
    float f_ = __shfl_down_sync(0xffffffffu, act, 1);
    float g_ = __shfl_down_sync(0xffffffffu, act, 2);
    float o_ = __shfl_down_sync(0xffffffffu, act, 3);
    c = first ? act * g_ : fmaf(f_, c, act * g_);
    return o_ * tanh_ap(c);
}

__device__ __forceinline__ float xin_value(const float* trajs, const float* preds,
                                           int w, int s, int f) {
    if (w == 0) return trajs[s * 4 + f];
    if (w < WS) {
        if (s < WS - w) return trajs[(w + s) * 4 + f];
        return (f < 2) ? trajs[(2 * w + s - 1) * 4 + f]
                       : preds[(w + s - WS) * 2 + (f - 2)];
    }
    return (f < 2) ? trajs[(w + s) * 4 + f]
                   : preds[(w + s - WS) * 2 + (f - 2)];
}

__global__ __launch_bounds__(256, 1)
void or_lstm_kernel(const float* __restrict__ traj,
                    const float* __restrict__ Wih0, const float* __restrict__ Whh0,
                    const float* __restrict__ bih0, const float* __restrict__ bhh0,
                    const float* __restrict__ Wih1, const float* __restrict__ Whh1,
                    const float* __restrict__ bih1, const float* __restrict__ bhh1,
                    const float* __restrict__ Wlin, const float* __restrict__ blin,
                    float* __restrict__ out)
{
    const int b    = blockIdx.x;
    const int tid  = threadIdx.x;
    const int m    = tid >> 2;
    const int sl   = tid & 3;
    const int wid  = tid >> 5;
    const int lane = tid & 31;

    __shared__ __align__(16) float trajs[TT * 4];
    __shared__ __align__(16) float h0buf[2][2][HH], h1buf[2][2][HH];  // [win parity][step parity]
    __shared__ __align__(16) u64 xgb01[2][WS][HH], xgb23[2][WS][HH];  // per window parity
    __shared__ __align__(16) u64 wp01s[HH * 4], wp23s[HH * 4];
    __shared__ __align__(16) u64 bp01s[HH], bp23s[HH];
    __shared__ float preds[NW * 2];
    __shared__ float predpart[16];
    __shared__ float blin_s[2];

    for (int i = tid; i < TT * 4; i += 256) trajs[i] = traj[b * TT * 4 + i];
    if (tid < 2) blin_s[tid] = blin[tid];
    {   // Wih0 / bias0 tables packed by gate pairs (i,f) and (g,o)
        const int mm = tid >> 2, f = tid & 3;
        wp01s[tid] = pack2(Wih0[mm * 4 + f],         Wih0[(64 + mm) * 4 + f]);
        wp23s[tid] = pack2(Wih0[(128 + mm) * 4 + f], Wih0[(192 + mm) * 4 + f]);
    }
    if (tid < 64) {
        bp01s[tid] = pack2(bih0[tid] + bhh0[tid],
                           bih0[64 + tid] + bhh0[64 + tid]);
        bp23s[tid] = pack2(bih0[128 + tid] + bhh0[128 + tid],
                           bih0[192 + tid] + bhh0[192 + tid]);
    }

    // ---- recurrent weights -> registers (thread (m,sl): 4 gate rows, 16-k slice) ----
    u64 whh0p[4][4][2], wih1p[4][4][2], whh1p[4][4][2];
    u64 b1p0, b1p1;
    {
        float bb1[4];
        #pragma unroll
        for (int g = 0; g < 4; g++) {
            const int rg = 64 * g + m;
            bb1[g] = bih1[rg] + bhh1[rg];
            #pragma unroll
            for (int c = 0; c < 4; c++) {
                const int k0 = 16 * c + 4 * sl;
                ulonglong2 v0 = *(const ulonglong2*)(Whh0 + rg * HH + k0);
                whh0p[g][c][0] = v0.x; whh0p[g][c][1] = v0.y;
                ulonglong2 v1 = *(const ulonglong2*)(Wih1 + rg * HH + k0);
                wih1p[g][c][0] = v1.x; wih1p[g][c][1] = v1.y;
                ulonglong2 v2 = *(const ulonglong2*)(Whh1 + rg * HH + k0);
                whh1p[g][c][0] = v2.x; whh1p[g][c][1] = v2.y;
            }
        }
        b1p0 = pack2(bb1[0], bb1[1]); b1p1 = pack2(bb1[2], bb1[3]);
    }
    const float wlreg = (sl < 2) ? Wlin[sl * 64 + m] : 0.0f;
    const float km = (sl == 2) ? 1.0f : 0.5f;
    const float kb = (sl == 2) ? 0.0f : 0.5f;

    float c0A = 0.f, c1A = 0.f;   // even-window cell state (valid in sl==0 lanes)
    float c0B = 0.f, c1B = 0.f;   // odd-window cell state

    // one warp builds one xgb row for (window parity pi, window w, step s)
    auto xgb_row = [&](int pi, int w, int s) {
        float xf = (lane < 4) ? xin_value(trajs, preds, w, s, lane) : 0.0f;
        u64 px[4];
        #pragma unroll
        for (int f = 0; f < 4; f++) {
            float x = __shfl_sync(0xffffffffu, xf, f);
            px[f] = pack2(x, x);
        }
        #pragma unroll
        for (int r = 0; r < 2; r++) {
            const int mm = lane + 32 * r;
            u64 a01 = bp01s[mm], a23 = bp23s[mm];
            #pragma unroll
            for (int f = 0; f < 4; f++) {
                fma2(a01, px[f], wp01s[mm * 4 + f]);
                fma2(a23, px[f], wp23s[mm * 4 + f]);
            }
            xgb01[pi][s][mm] = a01; xgb23[pi][s][mm] = a23;
        }
    };

    // P0(0): cell from xgb only (zero init state)
    auto p0_first = [&](int pi, float& c0r) {
        u64 A0 = xgb01[pi][0][m], B0 = xgb23[pi][0][m];
        float act0 = gate_act(A0, B0, sl, km, kb);
        float h0 = cell_from_act(act0, c0r, true);
        if (sl == 0) h0buf[pi][0][m] = h0;
    };
    // P1(0){first} + P0(1)
    auto step_s1 = [&](int pi, float& c0r, float& c1r) {
        u64 a1[4] = {0,0,0,0}, a0[4] = {0,0,0,0};
        const float* h0p = h0buf[pi][0];
        #pragma unroll
        for (int c = 0; c < 4; c++) {
            ulonglong2 hv = *(const ulonglong2*)(h0p + 16 * c + 4 * sl);
            #pragma unroll
            for (int g = 0; g < 4; g++) {
                fma2(a1[g], hv.x, wih1p[g][c][0]); fma2(a1[g], hv.y, wih1p[g][c][1]);
                fma2(a0[g], hv.x, whh0p[g][c][0]); fma2(a0[g], hv.y, whh0p[g][c][1]);
            }
        }
        u64 A1 = reduce_pair(pack2(hsum(a1[0]), hsum(a1[1])));
        u64 B1 = reduce_pair(pack2(hsum(a1[2]), hsum(a1[3])));
        add2(A1, b1p0); add2(B1, b1p1);
        float h1 = cell_from_act(gate_act(A1, B1, sl, km, kb), c1r, true);
        if (sl == 0) h1buf[pi][0][m] = h1;
        u64 A0 = reduce_pair(pack2(hsum(a0[0]), hsum(a0[1])));
        u64 B0 = reduce_pair(pack2(hsum(a0[2]), hsum(a0[3])));
        add2(A0, xgb01[pi][1][m]); add2(B0, xgb23[pi][1][m]);
        float h0 = cell_from_act(gate_act(A0, B0, sl, km, kb), c0r, false);
        if (sl == 0) h0buf[pi][1][m] = h0;
    };
    // P1(s-1) + P0(s), s in 2..7
    auto step_full = [&](int pi, int s, float& c0r, float& c1r) {
        u64 a1[4] = {0,0,0,0}, a0[4] = {0,0,0,0};
        const float* h0p = h0buf[pi][(s - 1) & 1];
        #pragma unroll
        for (int c = 0; c < 4; c++) {
            ulonglong2 hv = *(const ulonglong2*)(h0p + 16 * c + 4 * sl);
            #pragma unroll
            for (int g = 0; g < 4; g++) {
                fma2(a1[g], hv.x, wih1p[g][c][0]); fma2(a1[g], hv.y, wih1p[g][c][1]);
                fma2(a0[g], hv.x, whh0p[g][c][0]); fma2(a0[g], hv.y, whh0p[g][c][1]);
            }
        }
        dot64(a1, h1buf[pi][s & 1], whh1p, sl);    // h1(s-2): (s-2)&1 == s&1
        u64 A1 = reduce_pair(pack2(hsum(a1[0]), hsum(a1[1])));
        u64 B1 = reduce_pair(pack2(hsum(a1[2]), hsum(a1[3])));
        add2(A1, b1p0); add2(B1, b1p1);
        float h1 = cell_from_act(gate_act(A1, B1, sl, km, kb), c1r, false);
        if (sl == 0) h1buf[pi][(s - 1) & 1][m] = h1;
        u64 A0 = reduce_pair(pack2(hsum(a0[0]), hsum(a0[1])));
        u64 B0 = reduce_pair(pack2(hsum(a0[2]), hsum(a0[3])));
        add2(A0, xgb01[pi][s][m]); add2(B0, xgb23[pi][s][m]);
        float h0 = cell_from_act(gate_act(A0, B0, sl, km, kb), c0r, false);
        if (sl == 0) h0buf[pi][s & 1][m] = h0;
    };
    // P1(7) + Wlin·h1 partial
    auto step_tail = [&](int pi, float& c1r) {
        u64 a1[4] = {0,0,0,0};
        dot64(a1, h0buf[pi][1], wih1p, sl);        // h0(7)
        dot64(a1, h1buf[pi][0], whh1p, sl);        // h1(6)
        u64 A1 = reduce_pair(pack2(hsum(a1[0]), hsum(a1[1])));
        u64 B1 = reduce_pair(pack2(hsum(a1[2]), hsum(a1[3])));
        add2(A1, b1p0); add2(B1, b1p1);
        float h1 = cell_from_act(gate_act(A1, B1, sl, km, kb), c1r, false);
        if (sl == 0) h1buf[pi][1][m] = h1;
        float hb = __shfl_sync(0xffffffffu, h1, lane & ~3);
        float pv = wlreg * hb;
        pv += __shfl_xor_sync(0xffffffffu, pv, 4);
        pv += __shfl_xor_sync(0xffffffffu, pv, 8);
        pv += __shfl_xor_sync(0xffffffffu, pv, 16);
        if (lane < 2) predpart[wid * 2 + lane] = pv;
    };

    // one super-iteration = 5 phases; carries window w (new) and window w-1 (old)
    auto super_iter = [&](int w, float& c0w, float& c1w, float& c0v, float& c1v) {
        const int pw = w & 1, pv_ = pw ^ 1;
        const bool dw = (w < NW), dv = (w >= 1);
        // φ0: [w-1: P1(4)+P0(5)] [w: P0(0)]  sides: xgb row6(w), row7(w-1)
        if (dv) step_full(pv_, 5, c0v, c1v);
        if (dw) p0_first(pw, c0w);
        if (dw && w >= 1 && wid == 6) xgb_row(pw, w, 6);
        if (w >= 2 && wid == 7) xgb_row(pv_, w - 1, 7);
        __syncthreads();
        // φ1: [w-1: P1(5)+P0(6)] [w: P1(0)+P0(1)]
        if (dv) step_full(pv_, 6, c0v, c1v);
        if (dw) step_s1(pw, c0w, c1w);
        __syncthreads();
        // φ2: [w-1: P1(6)+P0(7)] [w: P1(1)+P0(2)]
        if (dv) step_full(pv_, 7, c0v, c1v);
        if (dw) step_full(pw, 2, c0w, c1w);
        __syncthreads();
        // φ3: [w-1: P1(7)+predpart] [w: P1(2)+P0(3)]
        if (dv) step_tail(pv_, c1v);
        if (dw) step_full(pw, 3, c0w, c1w);
        __syncthreads();
        // φ4: [w: P1(3)+P0(4)] [finalize pred[w-1]] [xgb rows 0..5 of w+1]
        if (dw) step_full(pw, 4, c0w, c1w);
        if (dv && wid == 7 && lane < 2) {
            const int wv = w - 1;
            float d = blin_s[lane];
            #pragma unroll
            for (int k = 0; k < 8; k++) d += predpart[k * 2 + lane];
            const float prev = (wv == 0) ? trajs[7 * 4 + 2 + lane]
                                         : preds[(wv - 1) * 2 + lane];
            const float pr = prev + d;
            preds[wv * 2 + lane] = pr;
            out[(b * NW + wv) * 2 + lane] = pr;
        }
        if ((w + 1) < NW && wid < 6) xgb_row((w + 1) & 1, w + 1, wid);
        __syncthreads();
    };

    __syncthreads();          // staging done
    xgb_row(0, 0, wid);       // all 8 rows of window 0 (pure traj)
    __syncthreads();

    for (int w2 = 0; w2 < NW; w2 += 2) {
        super_iter(w2,     c0A, c1A, c0B, c1B);
        super_iter(w2 + 1, c0B, c1B, c0A, c1A);
    }
    super_iter(NW, c0A, c1A, c0B, c1B);   // tail: finishes window 247 (odd, state B)

    // ---- final states: h[2,B,H] then c[2,B,H]; window 247 = parity 1 ----
    if (sl == 0) {
        const int base = BB * NW * 2;
        out[base + 0 * BB * HH + b * HH + m] = h0buf[1][1][m];
        out[base + 1 * BB * HH + b * HH + m] = h1buf[1][1][m];
        out[base + 2 * BB * HH + b * HH + m] = c0B;
        out[base + 3 * BB * HH + b * HH + m] = c1B;
    }
}

extern "C" void kernel_launch(void* const* d_in, const int* in_sizes, int n_in,
                              void* d_out, int out_size) {
    const float* traj = (const float*)d_in[0];
    const float* Wih0 = (const float*)d_in[1];
    const float* Whh0 = (const float*)d_in[2];
    const float* bih0 = (const float*)d_in[3];
    const float* bhh0 = (const float*)d_in[4];
    const float* Wih1 = (const float*)d_in[5];
    const float* Whh1 = (const float*)d_in[6];
    const float* bih1 = (const float*)d_in[7];
    const float* bhh1 = (const float*)d_in[8];
    const float* Wlin = (const float*)d_in[9];
    const float* blin = (const float*)d_in[10];

    or_lstm_kernel<<<BB, 256>>>(traj, Wih0, Whh0, bih0, bhh0,
                                Wih1, Whh1, bih1, bhh1,
                                Wlin, blin, (float*)d_out);
}